// round 13
// baseline (speedup 1.0000x reference)
#include <cuda_runtime.h>

// Shapes fixed by setup_inputs
#define B_ 64
#define T_ 4096
#define F_ 64
#define H_ 256
#define EPSV 1e-8f

// Chunked scan: lambda=0.5 -> 32-step warm-up error ~0.5^32.
#define CHUNK 64
#define NCHUNK (T_ / CHUNK)        // 64
#define WARM 32

#define NSC (B_ * NCHUNK)          // 4096 scan chunks
#define NFG 1024                   // fg blocks, 256 rows each
#define NM 16                      // mse blocks
#define NB1 (NSC + NFG + NM)       // 5136

#define ND2 256                    // dot blocks in kernel 2

__device__ float g_irrsum[B_ * T_];   // sum_f (1-|ac|) per (b,t)
__device__ float g_fgsum[B_ * T_];    // sum_h fg per (b,t)
__device__ float g_mse[NM];
__device__ float g_dot[ND2];
__device__ unsigned int g_cnt = 0;

// ---------------------------------------------------------------------------
// Kernel 1: independent roles, interleaved 4 scan : 1 fg so each SM hosts
// latency-bound scan warps AND high-MLP BW-bound fg warps concurrently.
//   scan role: 64 thr = one (b,chunk). |ac| -> smem tile, transpose-sum at
//              end (no per-step shfl). Writes g_irrsum[64].
//   fg role:   64 thr, 256 rows. Octet layout: 8 lanes/row, 8 independent
//              LDG.128 per lane (MLP=8), 3-shfl reduce. Writes g_fgsum.
// ---------------------------------------------------------------------------
__global__ void __launch_bounds__(64) k_main(const float* __restrict__ seq,
                                             const float4* __restrict__ fg,
                                             const float4* __restrict__ inp,
                                             const float4* __restrict__ tgt) {
    __shared__ float irr[CHUNK][65];        // padded: conflict-free both ways
    __shared__ float sh[2];

    int tid = threadIdx.x;
    int warp = tid >> 5, lane = tid & 31;
    int bid = blockIdx.x;

    if (bid < NSC + NFG) {
        int gq = bid / 5, r = bid - gq * 5;
        if (r < 4) {
            // ================= scan role =================
            int si = gq * 4 + r;               // 0..4095
            int b = si >> 6;                   // NCHUNK=64
            int chunk = si & 63;
            int t0 = chunk * CHUNK;

            const float* base = seq + (size_t)b * T_ * F_ + tid;
            int first = (chunk == 0);
            int ts = first ? 1 : (t0 - WARM);

            float m = 0.f, v = EPSV, c = 0.f;
            float xl = __ldg(base + (size_t)(ts - 1) * F_);

            // warm-up (no output)
#pragma unroll 8
            for (int t = ts; t < t0; ++t) {
                float xt = __ldg(base + (size_t)t * F_);
                m = 0.5f * (m + xt);
                float d = xt - m;
                v = 0.5f * (v + d * d);
                c = 0.5f * (c + d * (xl - m));
                xl = xt;
            }

            if (first) irr[0][tid] = 0.f;      // t=0 pad: |ac| = 0
            int tb = first ? 1 : t0;
#pragma unroll 8
            for (int t = tb; t < t0 + CHUNK; ++t) {
                float xt = __ldg(base + (size_t)t * F_);
                m = 0.5f * (m + xt);
                float d = xt - m;
                v = 0.5f * (v + d * d);
                c = 0.5f * (c + d * (xl - m));
                xl = xt;
                irr[t - t0][tid] = fabsf(c * rsqrtf(v * v + EPSV));
            }
            __syncthreads();

            // transpose-sum: thread tid owns timestep tid
            float s = 0.f;
#pragma unroll 16
            for (int f = 0; f < F_; ++f) s += irr[tid][f];
            g_irrsum[b * T_ + t0 + tid] = (float)F_ - s;
        } else {
            // ================= fg role (high MLP) =================
            int fgi = gq;                       // 0..1023, 256 rows each
            const float4* fgb = fg + (size_t)fgi * 256 * (H_ / 4);
            float* outp = g_fgsum + fgi * 256;
            int sub = lane >> 3;                // row within pass
            int col0 = lane & 7;                // float4 column start
#pragma unroll 4
            for (int pass = 0; pass < 32; ++pass) {
                int rr = warp * 128 + pass * 4 + sub;
                const float4* rp = fgb + (size_t)rr * (H_ / 4) + col0;
                float4 a0 = rp[0],  a1 = rp[8],  a2 = rp[16], a3 = rp[24];
                float4 a4 = rp[32], a5 = rp[40], a6 = rp[48], a7 = rp[56];
                float s =
                  (((a0.x + a0.y) + (a0.z + a0.w)) + ((a1.x + a1.y) + (a1.z + a1.w))) +
                  (((a2.x + a2.y) + (a2.z + a2.w)) + ((a3.x + a3.y) + (a3.z + a3.w))) +
                  (((a4.x + a4.y) + (a4.z + a4.w)) + ((a5.x + a5.y) + (a5.z + a5.w))) +
                  (((a6.x + a6.y) + (a6.z + a6.w)) + ((a7.x + a7.y) + (a7.z + a7.w)));
                s += __shfl_xor_sync(0xffffffffu, s, 1);
                s += __shfl_xor_sync(0xffffffffu, s, 2);
                s += __shfl_xor_sync(0xffffffffu, s, 4);
                if (col0 == 0) outp[rr] = s;
            }
        }
    } else {
        // ================= MSE role =================
        int mi = bid - (NSC + NFG);
        const int n4 = (B_ * T_) / 4;
        float acc = 0.f;
        for (int i = mi * 64 + tid; i < n4; i += NM * 64) {
            float4 a = inp[i], b = tgt[i];
            float dx = a.x - b.x, dy = a.y - b.y, dz = a.z - b.z, dw = a.w - b.w;
            acc += dx * dx + dy * dy + dz * dz + dw * dw;
        }
#pragma unroll
        for (int o = 16; o > 0; o >>= 1) acc += __shfl_xor_sync(0xffffffffu, acc, o);
        if (lane == 0) sh[warp] = acc;
        __syncthreads();
        if (tid == 0) g_mse[mi] = (sh[0] + sh[1]) * (1.0f / ((float)B_ * T_));
    }
}

// ---------------------------------------------------------------------------
// Kernel 2: dot(g_irrsum, g_fgsum) with high parallelism; last block folds
// in MSE partials and writes the scalar.
// ---------------------------------------------------------------------------
__global__ void __launch_bounds__(256) k_dot2(float* __restrict__ out) {
    __shared__ float sh[8];
    __shared__ int is_last;
    int tid = threadIdx.x;
    int warp = tid >> 5, lane = tid & 31;

    const float4* ir4 = (const float4*)g_irrsum;
    const float4* fs4 = (const float4*)g_fgsum;

    // 65536 float4 pairs over 256*256 threads: exactly one each
    int i = blockIdx.x * 256 + tid;
    float4 a = ir4[i], b = fs4[i];
    float acc = a.x * b.x + a.y * b.y + a.z * b.z + a.w * b.w;

#pragma unroll
    for (int o = 16; o > 0; o >>= 1) acc += __shfl_xor_sync(0xffffffffu, acc, o);
    if (lane == 0) sh[warp] = acc;
    __syncthreads();
    if (tid == 0) {
        float s = 0.f;
        for (int w = 0; w < 8; ++w) s += sh[w];
        // ALPHA / (B*T*H*F) = 0.5 / 2^32
        g_dot[blockIdx.x] = s * (0.5f / 4294967296.0f);
        __threadfence();
        unsigned int t = atomicAdd(&g_cnt, 1u);
        is_last = (t == ND2 - 1);
    }
    __syncthreads();
    if (is_last) {
        double s = 0.0;
        for (int i2 = tid; i2 < ND2; i2 += 256) s += (double)g_dot[i2];
        if (tid < NM) s += (double)g_mse[tid];
#pragma unroll
        for (int o = 16; o > 0; o >>= 1) s += __shfl_xor_sync(0xffffffffu, s, o);
        __shared__ double sd[8];
        if (lane == 0) sd[warp] = s;
        __syncthreads();
        if (tid == 0) {
            double tot = 0.0;
            for (int w = 0; w < 8; ++w) tot += sd[w];
            out[0] = (float)tot;
            g_cnt = 0;                        // reset for graph replay
        }
    }
}

// ---------------------------------------------------------------------------
extern "C" void kernel_launch(void* const* d_in, const int* in_sizes, int n_in,
                              void* d_out, int out_size) {
    const float* input  = (const float*)d_in[0];
    const float* target = (const float*)d_in[1];
    const float* seq    = (const float*)d_in[2];
    const float* fg     = (const float*)d_in[3];

    k_main<<<NB1, 64>>>(seq, (const float4*)fg,
                        (const float4*)input, (const float4*)target);
    k_dot2<<<ND2, 256>>>((float*)d_out);
}

// round 14
// speedup vs baseline: 1.0151x; 1.0151x over previous
#include <cuda_runtime.h>

// Shapes fixed by setup_inputs
#define B_ 64
#define T_ 4096
#define F_ 64
#define H_ 256
#define EPSV 1e-8f

// Chunked scan: lambda=0.5 -> 32-step warm-up error ~0.5^32.
#define CHUNK 64
#define NCHUNK (T_ / CHUNK)        // 64
#define WARM 32

#define NSC (B_ * NCHUNK)          // 4096 scan chunks
#define NGRP (NSC / 4)             // 1024 groups: 4 scan blocks + 1 fg block
#define NM 16                      // mse blocks
#define NB (NGRP * 5 + NM)         // 5136
#define NPART (NGRP + NM)          // 1040 partials

__device__ float g_irrsum[B_ * T_];   // sum_f (1-|ac|) per (b,t), tile-flagged
__device__ int   g_flag[NSC];         // zero-init; reset by consumer each run
__device__ float g_part[NPART];
__device__ unsigned int g_cnt = 0;

// ---------------------------------------------------------------------------
// Single kernel, dependency-reversed roles (4 scan : 1 fg per group of 5):
//   scan block (bid 5g+r, r<4): chunk si=4g+r. R8-proven loop: per-t |ac|
//     5-shfl warp reduce into smem, writes g_irrsum[si*64..], sets flag.
//   fg block (bid 5g+4): octet-MLP reduce of fg rows [g*256, g*256+256) into
//     SMEM (no gmem round-trip), waits on its 4 producer flags (all smaller
//     bids -> scheduled earlier -> no deadlock), dots locally -> g_part[g].
//   mse blocks at the end -> g_part[1024+mi].
// Last arriving of the 1040 g_part writers reduces to the output scalar.
// ---------------------------------------------------------------------------
__global__ void __launch_bounds__(64) k_main(const float* __restrict__ seq,
                                             const float4* __restrict__ fg,
                                             const float4* __restrict__ inp,
                                             const float4* __restrict__ tgt,
                                             float* __restrict__ out) {
    __shared__ float ws[2][CHUNK];     // scan: per-warp per-t partials
    __shared__ float fgs[256];         // fg: row sums for this tile
    __shared__ float sh[2];
    __shared__ int is_last;

    int tid = threadIdx.x;
    int warp = tid >> 5, lane = tid & 31;
    int bid = blockIdx.x;

    if (bid < NGRP * 5) {
        int gq = bid / 5, r = bid - gq * 5;
        if (r < 4) {
            // ================= scan role =================
            int si = gq * 4 + r;               // chunk index 0..4095
            int b = si >> 6;
            int chunk = si & 63;
            int t0 = chunk * CHUNK;

            const float* base = seq + (size_t)b * T_ * F_ + tid;
            int first = (chunk == 0);
            int ts = first ? 1 : (t0 - WARM);

            float m = 0.f, v = EPSV, c = 0.f;
            float xl = __ldg(base + (size_t)(ts - 1) * F_);

            // warm-up (no output)
#pragma unroll 8
            for (int t = ts; t < t0; ++t) {
                float xt = __ldg(base + (size_t)t * F_);
                m = 0.5f * (m + xt);
                float d = xt - m;
                v = 0.5f * (v + d * d);
                c = 0.5f * (c + d * (xl - m));
                xl = xt;
            }

            if (first && tid < 2) ws[tid][0] = 0.f;   // t=0 pad: |ac| = 0
            int tb = first ? 1 : t0;
#pragma unroll 8
            for (int t = tb; t < t0 + CHUNK; ++t) {
                float xt = __ldg(base + (size_t)t * F_);
                m = 0.5f * (m + xt);
                float d = xt - m;
                v = 0.5f * (v + d * d);
                c = 0.5f * (c + d * (xl - m));
                xl = xt;
                float a = fabsf(c * rsqrtf(v * v + EPSV));
#pragma unroll
                for (int o = 16; o > 0; o >>= 1) a += __shfl_xor_sync(0xffffffffu, a, o);
                if (lane == 0) ws[warp][t - t0] = a;
            }
            __syncthreads();
            // irrsum_t = F - sum_f |ac|; one coalesced 256B store
            g_irrsum[si * CHUNK + tid] = (float)F_ - ws[0][tid] - ws[1][tid];
            __threadfence();
            __syncthreads();
            if (tid == 0) ((volatile int*)g_flag)[si] = 1;   // release
            return;                                          // no finalize part
        } else {
            // ================= fg role (high MLP, consumer) =================
            const float4* fgb = fg + (size_t)gq * 256 * (H_ / 4);
            int sub = lane >> 3;                // row within pass
            int col0 = lane & 7;                // float4 column start
#pragma unroll 4
            for (int pass = 0; pass < 32; ++pass) {
                int rr = warp * 128 + pass * 4 + sub;
                const float4* rp = fgb + (size_t)rr * (H_ / 4) + col0;
                float4 a0 = rp[0],  a1 = rp[8],  a2 = rp[16], a3 = rp[24];
                float4 a4 = rp[32], a5 = rp[40], a6 = rp[48], a7 = rp[56];
                float s =
                  (((a0.x + a0.y) + (a0.z + a0.w)) + ((a1.x + a1.y) + (a1.z + a1.w))) +
                  (((a2.x + a2.y) + (a2.z + a2.w)) + ((a3.x + a3.y) + (a3.z + a3.w))) +
                  (((a4.x + a4.y) + (a4.z + a4.w)) + ((a5.x + a5.y) + (a5.z + a5.w))) +
                  (((a6.x + a6.y) + (a6.z + a6.w)) + ((a7.x + a7.y) + (a7.z + a7.w)));
                s += __shfl_xor_sync(0xffffffffu, s, 1);
                s += __shfl_xor_sync(0xffffffffu, s, 2);
                s += __shfl_xor_sync(0xffffffffu, s, 4);
                if (col0 == 0) fgs[rr] = s;
            }
            __syncthreads();

            // wait for the 4 irrsum producers (smaller bids; long finished)
            if (tid < 4) {
                while (((volatile int*)g_flag)[gq * 4 + tid] == 0) __nanosleep(64);
            }
            __threadfence();                    // acquire
            __syncthreads();

            float acc = 0.f;
#pragma unroll
            for (int j = 0; j < 4; ++j)
                acc += g_irrsum[(gq * 4 + j) * CHUNK + tid] * fgs[j * 64 + tid];
#pragma unroll
            for (int o = 16; o > 0; o >>= 1) acc += __shfl_xor_sync(0xffffffffu, acc, o);
            if (lane == 0) sh[warp] = acc;
            __syncthreads();
            if (tid == 0) {
                // ALPHA / (B*T*H*F) = 0.5 / 2^32
                g_part[gq] = (sh[0] + sh[1]) * (0.5f / 4294967296.0f);
            }
            __syncthreads();
            if (tid < 4) g_flag[gq * 4 + tid] = 0;   // reset for next replay
        }
    } else {
        // ================= MSE role =================
        int mi = bid - NGRP * 5;
        const int n4 = (B_ * T_) / 4;
        float acc = 0.f;
        for (int i = mi * 64 + tid; i < n4; i += NM * 64) {
            float4 a = inp[i], b = tgt[i];
            float dx = a.x - b.x, dy = a.y - b.y, dz = a.z - b.z, dw = a.w - b.w;
            acc += dx * dx + dy * dy + dz * dz + dw * dw;
        }
#pragma unroll
        for (int o = 16; o > 0; o >>= 1) acc += __shfl_xor_sync(0xffffffffu, acc, o);
        if (lane == 0) sh[warp] = acc;
        __syncthreads();
        if (tid == 0)
            g_part[NGRP + mi] = (sh[0] + sh[1]) * (1.0f / ((float)B_ * T_));
    }

    // ---- last-arrival finalize over the 1040 g_part writers ----
    if (tid == 0) {
        __threadfence();
        unsigned int t = atomicAdd(&g_cnt, 1u);
        is_last = (t == NPART - 1);
    }
    __syncthreads();
    if (is_last) {
        double s = 0.0;
        for (int i = tid; i < NPART; i += 64) s += (double)g_part[i];
#pragma unroll
        for (int o = 16; o > 0; o >>= 1) s += __shfl_xor_sync(0xffffffffu, s, o);
        __shared__ double sd[2];
        if (lane == 0) sd[warp] = s;
        __syncthreads();
        if (tid == 0) {
            out[0] = (float)(sd[0] + sd[1]);
            g_cnt = 0;                       // reset for next graph replay
        }
    }
}

// ---------------------------------------------------------------------------
extern "C" void kernel_launch(void* const* d_in, const int* in_sizes, int n_in,
                              void* d_out, int out_size) {
    const float* input  = (const float*)d_in[0];
    const float* target = (const float*)d_in[1];
    const float* seq    = (const float*)d_in[2];
    const float* fg     = (const float*)d_in[3];

    k_main<<<NB, 64>>>(seq, (const float4*)fg,
                       (const float4*)input, (const float4*)target,
                       (float*)d_out);
}

// round 15
// speedup vs baseline: 1.3758x; 1.3553x over previous
#include <cuda_runtime.h>

// Shapes fixed by setup_inputs
#define B_ 64
#define T_ 4096
#define F_ 64
#define H_ 256
#define EPSV 1e-8f

// Chunked scan: lambda=0.5 -> 32-step warm-up error ~0.5^32.
#define CHUNK 64
#define NCHUNK (T_ / CHUNK)        // 64
#define WARM 32

#define NS (B_ * NCHUNK)           // 4096 scan blocks
#define NM 16                      // mse blocks
#define NB (NS + NM)

__device__ float g_part[NB];
__device__ unsigned int g_cnt = 0;

// ---------------------------------------------------------------------------
// Fused kernel with PHASE-ORDER PARITY to break chip-wide phase lock-step:
//   even blocks: fg reduction -> scan (private acc)        [R6-proven path]
//   odd  blocks: scan (per-t shfl into smem) -> fg -> dot  [R8-proven pieces]
// At any wall-clock instant ~half the resident blocks stream forget_gates
// (DRAM-bound) while the other half run the recurrence (latency-bound).
//  [NS, NB): MSE partial blocks. Last arriving block finalizes (threadfence).
// ---------------------------------------------------------------------------
__global__ void __launch_bounds__(64) k_main(const float* __restrict__ seq,
                                             const float4* __restrict__ fg,
                                             const float4* __restrict__ inp,
                                             const float4* __restrict__ tgt,
                                             float* __restrict__ out) {
    __shared__ float fgsum_s[CHUNK];
    __shared__ float ws[2][CHUNK];
    __shared__ float sh[2];
    __shared__ int is_last;

    int tid = threadIdx.x;
    int warp = tid >> 5, lane = tid & 31;

    if (blockIdx.x < NS) {
        int b = blockIdx.x / NCHUNK;
        int chunk = blockIdx.x % NCHUNK;
        int t0 = chunk * CHUNK;
        int first = (chunk == 0);
        int ts = first ? 1 : (t0 - WARM);
        const float* base = seq + (size_t)b * T_ * F_ + tid;
        const float4* fgb = fg + (size_t)(b * T_ + t0) * (H_ / 4);

        if ((blockIdx.x & 1) == 0) {
            // ================= EVEN: fg -> scan (R6 path) =================
            // fg: warp-per-row pairs, float4
            int r0 = warp * (CHUNK / 2);
            for (int r = r0; r < r0 + CHUNK / 2; r += 2) {
                const float4* ra = fgb + (size_t)r * (H_ / 4);
                const float4* rb = ra + (H_ / 4);
                float4 a0 = ra[lane], a1 = ra[lane + 32];
                float4 b0 = rb[lane], b1 = rb[lane + 32];
                float s0 = (a0.x + a0.y) + (a0.z + a0.w) + (a1.x + a1.y) + (a1.z + a1.w);
                float s1 = (b0.x + b0.y) + (b0.z + b0.w) + (b1.x + b1.y) + (b1.z + b1.w);
#pragma unroll
                for (int o = 16; o > 0; o >>= 1) {
                    s0 += __shfl_xor_sync(0xffffffffu, s0, o);
                    s1 += __shfl_xor_sync(0xffffffffu, s1, o);
                }
                if (lane == 0) { fgsum_s[r] = s0; fgsum_s[r + 1] = s1; }
            }
            __syncthreads();

            float m = 0.f, v = EPSV, c = 0.f;
            float xl = __ldg(base + (size_t)(ts - 1) * F_);
            float acc = first ? fgsum_s[0] : 0.f;      // t=0 pad: irr==1
#pragma unroll 8
            for (int t = ts; t < t0; ++t) {
                float xt = __ldg(base + (size_t)t * F_);
                m = 0.5f * (m + xt);
                float d = xt - m;
                v = 0.5f * (v + d * d);
                c = 0.5f * (c + d * (xl - m));
                xl = xt;
            }
            int tb = first ? 1 : t0;
#pragma unroll 8
            for (int t = tb; t < t0 + CHUNK; ++t) {
                float xt = __ldg(base + (size_t)t * F_);
                m = 0.5f * (m + xt);
                float d = xt - m;
                v = 0.5f * (v + d * d);
                c = 0.5f * (c + d * (xl - m));
                xl = xt;
                float ac = c * rsqrtf(v * v + EPSV);
                acc += (1.0f - fabsf(ac)) * fgsum_s[t - t0];
            }
#pragma unroll
            for (int o = 16; o > 0; o >>= 1) acc += __shfl_xor_sync(0xffffffffu, acc, o);
            if (lane == 0) sh[warp] = acc;
            __syncthreads();
            if (tid == 0)
                g_part[blockIdx.x] = (sh[0] + sh[1]) * (0.5f / 4294967296.0f);
        } else {
            // ================= ODD: scan -> fg -> dot =================
            float m = 0.f, v = EPSV, c = 0.f;
            float xl = __ldg(base + (size_t)(ts - 1) * F_);
#pragma unroll 8
            for (int t = ts; t < t0; ++t) {            // warm-up
                float xt = __ldg(base + (size_t)t * F_);
                m = 0.5f * (m + xt);
                float d = xt - m;
                v = 0.5f * (v + d * d);
                c = 0.5f * (c + d * (xl - m));
                xl = xt;
            }
            if (first && tid < 2) ws[tid][0] = 0.f;    // t=0 pad: |ac| = 0
            int tb = first ? 1 : t0;
#pragma unroll 8
            for (int t = tb; t < t0 + CHUNK; ++t) {
                float xt = __ldg(base + (size_t)t * F_);
                m = 0.5f * (m + xt);
                float d = xt - m;
                v = 0.5f * (v + d * d);
                c = 0.5f * (c + d * (xl - m));
                xl = xt;
                float a = fabsf(c * rsqrtf(v * v + EPSV));
#pragma unroll
                for (int o = 16; o > 0; o >>= 1) a += __shfl_xor_sync(0xffffffffu, a, o);
                if (lane == 0) ws[warp][t - t0] = a;
            }
            __syncthreads();

            // fg reduction (same layout as even path)
            int r0 = warp * (CHUNK / 2);
            for (int r = r0; r < r0 + CHUNK / 2; r += 2) {
                const float4* ra = fgb + (size_t)r * (H_ / 4);
                const float4* rb = ra + (H_ / 4);
                float4 a0 = ra[lane], a1 = ra[lane + 32];
                float4 b0 = rb[lane], b1 = rb[lane + 32];
                float s0 = (a0.x + a0.y) + (a0.z + a0.w) + (a1.x + a1.y) + (a1.z + a1.w);
                float s1 = (b0.x + b0.y) + (b0.z + b0.w) + (b1.x + b1.y) + (b1.z + b1.w);
#pragma unroll
                for (int o = 16; o > 0; o >>= 1) {
                    s0 += __shfl_xor_sync(0xffffffffu, s0, o);
                    s1 += __shfl_xor_sync(0xffffffffu, s1, o);
                }
                if (lane == 0) { fgsum_s[r] = s0; fgsum_s[r + 1] = s1; }
            }
            __syncthreads();

            // dot: thread tid owns timestep tid
            float acc = ((float)F_ - ws[0][tid] - ws[1][tid]) * fgsum_s[tid];
#pragma unroll
            for (int o = 16; o > 0; o >>= 1) acc += __shfl_xor_sync(0xffffffffu, acc, o);
            if (lane == 0) sh[warp] = acc;
            __syncthreads();
            if (tid == 0)
                g_part[blockIdx.x] = (sh[0] + sh[1]) * (0.5f / 4294967296.0f);
        }
    } else {
        // ================= MSE role =================
        int bid = blockIdx.x - NS;
        const int n4 = (B_ * T_) / 4;
        float acc = 0.f;
        for (int i = bid * 64 + tid; i < n4; i += NM * 64) {
            float4 a = inp[i], b = tgt[i];
            float dx = a.x - b.x, dy = a.y - b.y, dz = a.z - b.z, dw = a.w - b.w;
            acc += dx * dx + dy * dy + dz * dz + dw * dw;
        }
#pragma unroll
        for (int o = 16; o > 0; o >>= 1) acc += __shfl_xor_sync(0xffffffffu, acc, o);
        if (lane == 0) sh[warp] = acc;
        __syncthreads();
        if (tid == 0)
            g_part[blockIdx.x] = (sh[0] + sh[1]) * (1.0f / ((float)B_ * T_));
    }

    // ---- last-block finalize (threadfence reduction, graph-replay safe) ----
    if (tid == 0) {
        __threadfence();
        unsigned int t = atomicAdd(&g_cnt, 1u);
        is_last = (t == NB - 1);
    }
    __syncthreads();
    if (is_last) {
        double s = 0.0;
        for (int i = tid; i < NB; i += 64) s += (double)g_part[i];
#pragma unroll
        for (int o = 16; o > 0; o >>= 1) s += __shfl_xor_sync(0xffffffffu, s, o);
        __shared__ double sd[2];
        if (lane == 0) sd[warp] = s;
        __syncthreads();
        if (tid == 0) {
            out[0] = (float)(sd[0] + sd[1]);
            g_cnt = 0;                       // reset for next graph replay
        }
    }
}

// ---------------------------------------------------------------------------
extern "C" void kernel_launch(void* const* d_in, const int* in_sizes, int n_in,
                              void* d_out, int out_size) {
    const float* input  = (const float*)d_in[0];
    const float* target = (const float*)d_in[1];
    const float* seq    = (const float*)d_in[2];
    const float* fg     = (const float*)d_in[3];

    k_main<<<NB, 64>>>(seq, (const float4*)fg,
                       (const float4*)input, (const float4*)target,
                       (float*)d_out);
}